// round 1
// baseline (speedup 1.0000x reference)
#include <cuda_runtime.h>

#define BB 8
#define CC 128
#define HH 64
#define WW 64
#define HWN 4096
#define PC 384          // perception channels = 3*CC
#define NP 49280        // 3*CC*CC + CC
#define LAT 512
#define NSTEP 32
#define EPSV 1e-5f

// d_out layout (float32), concatenated in return order:
//  [0, 98304)                       : clip(out[:, :3], -1, 1)   (8,3,64,64)
//  [98304, 98304+138412032)         : out_embs (33,8,128,64,64)
//  [138510336, 138608640)           : out_raw  (8,3,64,64)
#define OFF_EMBS (BB*3*HWN)
#define EMB_SLICE (BB*CC*HWN)
#define OFF_RAW (OFF_EMBS + 33*EMB_SLICE)

__device__ float g_ybuf[BB * PC * HWN];    // normalized perception, 50.3 MB
__device__ float g_params[BB * NP];        // dynamic weights + bias

// ---------------------------------------------------------------------------
// params[b, p] = sum_k lat[b,k] * w_dyn[k,p] + b_dyn[p]
// ---------------------------------------------------------------------------
__global__ void params_kernel(const float* __restrict__ lat,
                              const float* __restrict__ w_dyn,
                              const float* __restrict__ b_dyn) {
    __shared__ float slat[BB * LAT];
    int tid = threadIdx.x;
    for (int i = tid; i < BB * LAT; i += blockDim.x) slat[i] = lat[i];
    __syncthreads();
    int p = blockIdx.x * blockDim.x + tid;
    if (p >= NP) return;
    float acc[BB];
#pragma unroll
    for (int b = 0; b < BB; b++) acc[b] = 0.f;
    for (int k = 0; k < LAT; k++) {
        float w = w_dyn[k * NP + p];
#pragma unroll
        for (int b = 0; b < BB; b++) acc[b] = fmaf(slat[b * LAT + k], w, acc[b]);
    }
    float bd = b_dyn[p];
#pragma unroll
    for (int b = 0; b < BB; b++) g_params[b * NP + p] = acc[b] + bd;
}

// ---------------------------------------------------------------------------
// embs[0] = seed: zeros except center pixel = 1 for every (b, c)
// ---------------------------------------------------------------------------
__global__ void seed_kernel(float* __restrict__ out) {
    float* e0 = out + OFF_EMBS;
    int n = EMB_SLICE;
    for (int i = blockIdx.x * blockDim.x + threadIdx.x; i < n;
         i += gridDim.x * blockDim.x) {
        int p = i & (HWN - 1);
        e0[i] = (p == (32 * 64 + 32)) ? 1.0f : 0.0f;
    }
}

// ---------------------------------------------------------------------------
// Perception + instance norm.  One block per (b, c).  Produces normalized
// [x, gx, gy] channels into g_ybuf.
// ---------------------------------------------------------------------------
__global__ __launch_bounds__(256) void perc_kernel(const float* __restrict__ state) {
    __shared__ __align__(16) float tile[HWN];
    __shared__ float red[6][8];
    __shared__ float tot[6];
    int bc = blockIdx.x;
    int b = bc >> 7, c = bc & 127;
    const float* xp = state + bc * HWN;
    int tid = threadIdx.x;

#pragma unroll
    for (int r = 0; r < 4; r++) {
        int f = tid + 256 * r;
        ((float4*)tile)[f] = ((const float4*)xp)[f];
    }
    __syncthreads();

    float xv[16], gxv[16], gyv[16];
    float s0 = 0, s1 = 0, s2 = 0, s3 = 0, s4 = 0, s5 = 0;
#pragma unroll
    for (int r = 0; r < 4; r++) {
        int f = tid + 256 * r;
        int p0 = f * 4;
        int i = p0 >> 6;
        int j0 = p0 & 63;
#pragma unroll
        for (int q = 0; q < 4; q++) {
            int j = j0 + q;
            float xm1m1 = (i > 0 && j > 0)   ? tile[(i - 1) * 64 + j - 1] : 0.f;
            float xm1c  = (i > 0)            ? tile[(i - 1) * 64 + j]     : 0.f;
            float xm1p1 = (i > 0 && j < 63)  ? tile[(i - 1) * 64 + j + 1] : 0.f;
            float x0m1  = (j > 0)            ? tile[i * 64 + j - 1]       : 0.f;
            float x0p1  = (j < 63)           ? tile[i * 64 + j + 1]       : 0.f;
            float xp1m1 = (i < 63 && j > 0)  ? tile[(i + 1) * 64 + j - 1] : 0.f;
            float xp1c  = (i < 63)           ? tile[(i + 1) * 64 + j]     : 0.f;
            float xp1p1 = (i < 63 && j < 63) ? tile[(i + 1) * 64 + j + 1] : 0.f;
            float xc = tile[i * 64 + j];
            float gx = ((xm1p1 - xm1m1) + 2.f * (x0p1 - x0m1) + (xp1p1 - xp1m1)) * 0.125f;
            float gy = ((xp1m1 - xm1m1) + 2.f * (xp1c - xm1c) + (xp1p1 - xm1p1)) * 0.125f;
            int idx = r * 4 + q;
            xv[idx] = xc; gxv[idx] = gx; gyv[idx] = gy;
            s0 += xc; s1 += xc * xc;
            s2 += gx; s3 += gx * gx;
            s4 += gy; s5 += gy * gy;
        }
    }
    // warp reduce 6 sums
    float s[6] = {s0, s1, s2, s3, s4, s5};
#pragma unroll
    for (int o = 16; o > 0; o >>= 1) {
#pragma unroll
        for (int q = 0; q < 6; q++) s[q] += __shfl_down_sync(0xffffffffu, s[q], o);
    }
    int warp = tid >> 5, lane = tid & 31;
    if (lane == 0) {
#pragma unroll
        for (int q = 0; q < 6; q++) red[q][warp] = s[q];
    }
    __syncthreads();
    if (tid < 6) {
        float t = 0;
#pragma unroll
        for (int w2 = 0; w2 < 8; w2++) t += red[tid][w2];
        tot[tid] = t;
    }
    __syncthreads();
    const float inv = 1.f / 4096.f;
    float mx  = tot[0] * inv;
    float mgx = tot[2] * inv;
    float mgy = tot[4] * inv;
    float rx  = rsqrtf(fmaxf(tot[1] * inv - mx * mx, 0.f) + EPSV);
    float rgx = rsqrtf(fmaxf(tot[3] * inv - mgx * mgx, 0.f) + EPSV);
    float rgy = rsqrtf(fmaxf(tot[5] * inv - mgy * mgy, 0.f) + EPSV);

    float* ybx  = g_ybuf + (b * PC + c) * HWN;
    float* ybgx = g_ybuf + (b * PC + CC + c) * HWN;
    float* ybgy = g_ybuf + (b * PC + 2 * CC + c) * HWN;
#pragma unroll
    for (int r = 0; r < 4; r++) {
        int f = tid + 256 * r;
        int p0 = f * 4;
        int base = r * 4;
        float4 a, g1, g2;
        a.x = (xv[base + 0] - mx) * rx;  a.y = (xv[base + 1] - mx) * rx;
        a.z = (xv[base + 2] - mx) * rx;  a.w = (xv[base + 3] - mx) * rx;
        g1.x = (gxv[base + 0] - mgx) * rgx; g1.y = (gxv[base + 1] - mgx) * rgx;
        g1.z = (gxv[base + 2] - mgx) * rgx; g1.w = (gxv[base + 3] - mgx) * rgx;
        g2.x = (gyv[base + 0] - mgy) * rgy; g2.y = (gyv[base + 1] - mgy) * rgy;
        g2.z = (gyv[base + 2] - mgy) * rgy; g2.w = (gyv[base + 3] - mgy) * rgy;
        *(float4*)(ybx + p0) = a;
        *(float4*)(ybgx + p0) = g1;
        *(float4*)(ybgy + p0) = g2;
    }
}

// ---------------------------------------------------------------------------
// next[b,o,p] = prev[b,o,p] + lf * (sum_i w[b,o,i]*y[b,i,p] + bias[b,o])
// block: 128 out x 128 pixels, 256 threads, 8x8 register micro-tile.
// ---------------------------------------------------------------------------
__global__ __launch_bounds__(256) void gemm_kernel(const float* __restrict__ lf_ptr,
                                                   const float* __restrict__ prev,
                                                   float* __restrict__ next) {
    __shared__ __align__(16) float Ws[8][128];
    __shared__ __align__(16) float Ys[8][128];
    int tid = threadIdx.x;
    int tx = tid & 15, ty = tid >> 4;
    int b = blockIdx.y;
    int pix0 = blockIdx.x * 128;
    const float* Y = g_ybuf + b * PC * HWN + pix0;
    const float* Wp = g_params + b * NP;

    float acc[8][8];
#pragma unroll
    for (int mi = 0; mi < 8; mi++)
#pragma unroll
        for (int ni = 0; ni < 8; ni++) acc[mi][ni] = 0.f;

    int wm = tid >> 1, wkk = (tid & 1) * 4;
    int yrow = tid >> 5, ycol = (tid & 31) * 4;

    for (int k0 = 0; k0 < PC; k0 += 8) {
        float4 w4 = *(const float4*)(Wp + wm * PC + k0 + wkk);
        Ws[wkk + 0][wm] = w4.x; Ws[wkk + 1][wm] = w4.y;
        Ws[wkk + 2][wm] = w4.z; Ws[wkk + 3][wm] = w4.w;
        *(float4*)&Ys[yrow][ycol] = *(const float4*)(Y + (k0 + yrow) * HWN + ycol);
        __syncthreads();
#pragma unroll
        for (int k = 0; k < 8; k++) {
            float4 a0 = *(float4*)&Ws[k][4 * ty];
            float4 a1 = *(float4*)&Ws[k][64 + 4 * ty];
            float4 b0 = *(float4*)&Ys[k][4 * tx];
            float4 b1 = *(float4*)&Ys[k][64 + 4 * tx];
            float av[8] = {a0.x, a0.y, a0.z, a0.w, a1.x, a1.y, a1.z, a1.w};
            float bv[8] = {b0.x, b0.y, b0.z, b0.w, b1.x, b1.y, b1.z, b1.w};
#pragma unroll
            for (int mi = 0; mi < 8; mi++)
#pragma unroll
                for (int ni = 0; ni < 8; ni++)
                    acc[mi][ni] = fmaf(av[mi], bv[ni], acc[mi][ni]);
        }
        __syncthreads();
    }

    float lf = fminf(fmaxf(*lf_ptr, 0.001f), 1000.f);
    const float* bias = Wp + 3 * CC * CC;
#pragma unroll
    for (int mi = 0; mi < 8; mi++) {
        int m = (mi < 4) ? (4 * ty + mi) : (64 + 4 * ty + mi - 4);
        float bo = bias[m];
        const float* pr = prev + (b * CC + m) * HWN + pix0;
        float* nx = next + (b * CC + m) * HWN + pix0;
#pragma unroll
        for (int nh = 0; nh < 2; nh++) {
            int n = (nh == 0) ? 4 * tx : 64 + 4 * tx;
            float4 pv = *(const float4*)(pr + n);
            float4 ov;
            ov.x = pv.x + lf * (acc[mi][nh * 4 + 0] + bo);
            ov.y = pv.y + lf * (acc[mi][nh * 4 + 1] + bo);
            ov.z = pv.z + lf * (acc[mi][nh * 4 + 2] + bo);
            ov.w = pv.w + lf * (acc[mi][nh * 4 + 3] + bo);
            *(float4*)(nx + n) = ov;
        }
    }
}

// ---------------------------------------------------------------------------
// Final: clip + raw copy of channels 0..2 from embs[32]
// ---------------------------------------------------------------------------
__global__ void final_kernel(float* __restrict__ out) {
    const float* st = out + OFF_EMBS + NSTEP * EMB_SLICE;
    int n = BB * 3 * HWN;
    int i = blockIdx.x * blockDim.x + threadIdx.x;
    if (i >= n) return;
    int p = i & (HWN - 1);
    int bc = i >> 12;
    int b = bc / 3, c = bc % 3;
    float v = st[(b * CC + c) * HWN + p];
    out[i] = fminf(fmaxf(v, -1.f), 1.f);
    out[OFF_RAW + i] = v;
}

extern "C" void kernel_launch(void* const* d_in, const int* in_sizes, int n_in,
                              void* d_out, int out_size) {
    const float* lat   = (const float*)d_in[0];
    const float* leak  = (const float*)d_in[1];
    const float* w_dyn = (const float*)d_in[2];
    const float* b_dyn = (const float*)d_in[3];
    float* out = (float*)d_out;

    params_kernel<<<(NP + 127) / 128, 128>>>(lat, w_dyn, b_dyn);
    seed_kernel<<<2048, 256>>>(out);
    for (int s = 0; s < NSTEP; s++) {
        const float* prev = out + OFF_EMBS + (size_t)s * EMB_SLICE;
        float* next = out + OFF_EMBS + (size_t)(s + 1) * EMB_SLICE;
        perc_kernel<<<BB * CC, 256>>>(prev);
        gemm_kernel<<<dim3(32, BB), 256>>>(leak, prev, next);
    }
    final_kernel<<<(BB * 3 * HWN + 255) / 256, 256>>>(out);
}